// round 14
// baseline (speedup 1.0000x reference)
#include <cuda_runtime.h>
#include <cuda_bf16.h>
#include <cuda_fp16.h>
#include <math.h>
#include <stdint.h>

// ---------------------------------------------------------------------------
// Problem constants
// ---------------------------------------------------------------------------
#define BB   16
#define CC   256
#define HH   56
#define WW   56
#define HW   3136
#define HWP  3200            // pixel dim padded
#define KK   7
#define GCC  16
#define GG   16
#define RED  64
#define KKG  784
#define PADI 3

// ---------------------------------------------------------------------------
// Scratch. Activations pixel-major [b][px][ch] fp16.
// wd channel-major [b][784][px] fp16. Weights fp16 (hi only used now).
// ---------------------------------------------------------------------------
__device__ __align__(16) __half g_x16[BB*HWP*CC];
__device__ __align__(16) __half g_y16[BB*HWP*CC];
__device__ __align__(16) __half g_r16[BB*HWP*RED];
__device__ __align__(16) __half g_z16[BB*HWP*CC];
__device__ __align__(16) __half g_wd[(size_t)BB*KKG*HWP];

__device__ __align__(16) __half g_w1h[CC*CC];
__device__ __align__(16) __half g_w3h[CC*CC];
__device__ __align__(16) __half g_rwh[128*CC];
__device__ __align__(16) __half g_swh[896*RED];

__device__ float g_s1[CC], g_h1[CC];
__device__ float g_sr[RED], g_hr[RED];
__device__ float g_s2[CC], g_h2[CC];
__device__ float g_s3[CC], g_h3[CC];

// ---------------------------------------------------------------------------
// PTX helpers
// ---------------------------------------------------------------------------
__device__ __forceinline__ uint32_t s2u(const void* p) {
    uint32_t a;
    asm("{ .reg .u64 t; cvta.to.shared.u64 t, %1; cvt.u32.u64 %0, t; }" : "=r"(a) : "l"(p));
    return a;
}

__device__ __forceinline__ void cpasync16(uint32_t saddr, const void* g) {
    asm volatile("cp.async.cg.shared.global [%0], [%1], 16;" :: "r"(saddr), "l"(g));
}

__device__ __forceinline__ void ldsm4(uint32_t* r, uint32_t a) {
    asm volatile("ldmatrix.sync.aligned.m8n8.x4.shared.b16 {%0,%1,%2,%3}, [%4];"
                 : "=r"(r[0]), "=r"(r[1]), "=r"(r[2]), "=r"(r[3]) : "r"(a));
}

__device__ __forceinline__ void mma_f16(float* c, const uint32_t* a, const uint32_t* b) {
    asm volatile("mma.sync.aligned.m16n8k16.row.col.f32.f16.f16.f32 "
        "{%0,%1,%2,%3}, {%4,%5,%6,%7}, {%8,%9}, {%0,%1,%2,%3};"
        : "+f"(c[0]), "+f"(c[1]), "+f"(c[2]), "+f"(c[3])
        : "r"(a[0]), "r"(a[1]), "r"(a[2]), "r"(a[3]), "r"(b[0]), "r"(b[1]));
}

__device__ __forceinline__ float tanha(float x) {
    float r; asm("tanh.approx.f32 %0, %1;" : "=f"(r) : "f"(x)); return r;
}

// Packed f32x2 (Blackwell family)
__device__ __forceinline__ void fma2(uint64_t& d, uint64_t a, uint64_t b) {
    asm("fma.rn.f32x2 %0, %1, %2, %0;" : "+l"(d) : "l"(a), "l"(b));
}
__device__ __forceinline__ uint64_t pack2(float x, float y) {
    uint64_t r; asm("mov.b64 %0, {%1, %2};" : "=l"(r) : "f"(x), "f"(y)); return r;
}
__device__ __forceinline__ void unpack2(float& x, float& y, uint64_t v) {
    asm("mov.b64 {%0, %1}, %2;" : "=f"(x), "=f"(y) : "l"(v));
}

// SW64-style swizzle for 64-byte rows
__device__ __forceinline__ uint32_t soff(int r, int c16) {
    return (uint32_t)(r * 64) + (uint32_t)(((c16 ^ ((r >> 1) & 3)) & 3) << 4);
}

// ---------------------------------------------------------------------------
// Fold BN (+conv bias) into per-channel scale/shift
// ---------------------------------------------------------------------------
__global__ void precompute_kernel(
    const float* __restrict__ b1,
    const float* __restrict__ g1, const float* __restrict__ be1,
    const float* __restrict__ m1, const float* __restrict__ v1,
    const float* __restrict__ redb,
    const float* __restrict__ rg, const float* __restrict__ rb,
    const float* __restrict__ rm, const float* __restrict__ rv,
    const float* __restrict__ g2, const float* __restrict__ be2,
    const float* __restrict__ m2, const float* __restrict__ v2,
    const float* __restrict__ b3,
    const float* __restrict__ g3, const float* __restrict__ be3,
    const float* __restrict__ m3, const float* __restrict__ v3)
{
    int c = threadIdx.x;
    if (c < CC) {
        float s = g1[c] * rsqrtf(v1[c] + 1e-5f);
        g_s1[c] = s; g_h1[c] = b1[c]*s + be1[c] - m1[c]*s;
        s = g2[c] * rsqrtf(v2[c] + 1e-5f);
        g_s2[c] = s; g_h2[c] = be2[c] - m2[c]*s;
        s = g3[c] * rsqrtf(v3[c] + 1e-5f);
        g_s3[c] = s; g_h3[c] = b3[c]*s + be3[c] - m3[c]*s;
    }
    if (c < RED) {
        float s = rg[c] * rsqrtf(rv[c] + 1e-5f);
        g_sr[c] = s; g_hr[c] = redb[c]*s + rb[c] - rm[c]*s;
    }
}

// ---------------------------------------------------------------------------
// Convert weights to fp16 (zero padding of M)
// ---------------------------------------------------------------------------
__global__ void prep_weights(const float* __restrict__ w1, const float* __restrict__ w3,
                             const float* __restrict__ redw, const float* __restrict__ spanw)
{
    int i = blockIdx.x * 256 + threadIdx.x;
    if (i < CC * CC) {
        g_w1h[i] = __float2half_rn(w1[i]);
        g_w3h[i] = __float2half_rn(w3[i]);
    }
    if (i < 128 * CC) {
        int r = i >> 8;
        g_rwh[i] = __float2half_rn((r < RED) ? redw[i] : 0.f);
    }
    if (i < 896 * RED) {
        int r = i / RED;
        g_swh[i] = __float2half_rn((r < KKG) ? spanw[i] : 0.f);
    }
}

// ---------------------------------------------------------------------------
// Transpose input x: [b][c][px] fp32 -> [b][px][c] fp16
// ---------------------------------------------------------------------------
__global__ void convert_x_kernel(const float* __restrict__ x)
{
    __shared__ float t[32][33];
    const int b = blockIdx.z, px0 = blockIdx.x * 32, c0 = blockIdx.y * 32;
    #pragma unroll
    for (int i = 0; i < 4; i++) {
        int cy = threadIdx.y + i * 8;
        t[cy][threadIdx.x] = x[((long)(b * CC + c0 + cy)) * HW + px0 + threadIdx.x];
    }
    __syncthreads();
    #pragma unroll
    for (int i = 0; i < 4; i++) {
        int py = threadIdx.y + i * 8;
        long a = ((long)b * HWP + px0 + py) * CC + c0 + threadIdx.x;
        g_x16[a] = __float2half_rn(t[threadIdx.x][py]);
    }
}

// ---------------------------------------------------------------------------
// fp16 GEMM on mma.sync: D[m, px] = W[m,:] . B[px,:]
// Block MT x 128 (m x px), 8 warps ((MT/2) x 32 warp tiles: 2m x 4px),
// K-chunk 32, 3-stage cp.async.
// EPI 0: tanh->fp16 [px][ch]   EPI 1: relu->fp16 [px][ch]
// EPI 2: v+shift -> fp16 wd [m][px]   EPI 3: v*sc+sh + resid -> fp32 NCHW
// ---------------------------------------------------------------------------
#define KC 32

template<int EPI, int MT>
__global__ __launch_bounds__(256, 2)
void gemm_tc(const __half* __restrict__ Ah, const __half* __restrict__ Bm,
             int Ka, int Mvalid, int Cs, int moff,
             float* __restrict__ outF, __half* __restrict__ O16,
             const float* __restrict__ scale, const float* __restrict__ shift,
             const float* __restrict__ resid)
{
    constexpr int MI    = MT / 32;           // 16-row m-subtiles per warp
    constexpr int OFFB  = MT * 64;           // A bytes per stage
    constexpr int STB   = (MT + 128) * 64;   // stage bytes

    extern __shared__ char smem[];
    const int tid = threadIdx.x, wid = tid >> 5, lane = tid & 31;
    const int b = blockIdx.z;
    const int m0 = blockIdx.y * MT + moff;
    const int px0 = blockIdx.x << 7;
    const uint32_t sb = s2u(smem);

    const int wm = (wid & 1) * (MT / 2);     // warp m offset
    const int wn = (wid >> 1) * 32;          // warp px offset

    const int lr = tid >> 2;                 // 0..63
    const int lc = tid & 3;
    const long bbase = (long)b * HWP + px0;

    float acc[MI][4][4];
    #pragma unroll
    for (int i = 0; i < MI; i++)
        #pragma unroll
        for (int j = 0; j < 4; j++)
            #pragma unroll
            for (int q = 0; q < 4; q++) acc[i][j][q] = 0.f;

    auto issue = [&](int kt, int s) {
        const int k0 = kt * KC;
        const uint32_t sbase = sb + s * STB;
        #pragma unroll
        for (int p = 0; p < MT / 64; p++) {
            int r = lr + p * 64;
            cpasync16(sbase + soff(r, lc), Ah + (long)(m0 + r) * Ka + k0 + lc * 8);
        }
        #pragma unroll
        for (int p = 0; p < 2; p++) {
            int r = lr + p * 64;
            cpasync16(sbase + OFFB + soff(r, lc), Bm + (bbase + r) * Ka + k0 + lc * 8);
        }
        asm volatile("cp.async.commit_group;" ::: "memory");
    };

    const int nk = Ka / KC;
    issue(0, 0);
    issue(1, 1);

    for (int t = 0; t < nk; t++) {
        if (t + 1 < nk) asm volatile("cp.async.wait_group 1;" ::: "memory");
        else            asm volatile("cp.async.wait_group 0;" ::: "memory");
        __syncthreads();
        if (t + 2 < nk) issue(t + 2, (t + 2) % 3);

        const uint32_t sbase = sb + (t % 3) * STB;

        // preload all B fragments for the chunk (warp's 32 px, both k16s)
        uint32_t bf[2][2][4];
        #pragma unroll
        for (int kb = 0; kb < 2; kb++)
            #pragma unroll
            for (int pr = 0; pr < 2; pr++) {
                int n = wn + pr * 16 + (lane & 7) + ((lane >> 4) << 3);
                int c = kb * 2 + ((lane >> 3) & 1);
                ldsm4(bf[kb][pr], sbase + OFFB + soff(n, c));
            }

        #pragma unroll
        for (int kb = 0; kb < 2; kb++) {
            #pragma unroll
            for (int mi = 0; mi < MI; mi++) {
                int r = wm + mi * 16 + (lane & 15);
                int c = kb * 2 + (lane >> 4);
                uint32_t ah[4];
                ldsm4(ah, sbase + soff(r, c));
                #pragma unroll
                for (int nt = 0; nt < 4; nt++)
                    mma_f16(acc[mi][nt], ah, &bf[kb][nt >> 1][(nt & 1) * 2]);
            }
        }
    }

    // ======================= smem-staged epilogue (two px halves) ========
    __syncthreads();
    float* sf = (float*)smem;
    const int g = lane >> 2, tg = lane & 3;

    #pragma unroll 1
    for (int half = 0; half < 2; half++) {
        if ((wn >> 6) == half) {
            if (EPI >= 2) {
                // [m][px] pitch 65
                #pragma unroll
                for (int mi = 0; mi < MI; mi++)
                    #pragma unroll
                    for (int nt = 0; nt < 4; nt++) {
                        int lpx = (wn & 63) + nt * 8 + tg * 2;
                        int lm  = wm + mi * 16 + g;
                        sf[lm * 65 + lpx]           = acc[mi][nt][0];
                        sf[lm * 65 + lpx + 1]       = acc[mi][nt][1];
                        sf[(lm + 8) * 65 + lpx]     = acc[mi][nt][2];
                        sf[(lm + 8) * 65 + lpx + 1] = acc[mi][nt][3];
                    }
            } else {
                // [px][m] pitch MT+1
                #pragma unroll
                for (int mi = 0; mi < MI; mi++)
                    #pragma unroll
                    for (int nt = 0; nt < 4; nt++) {
                        int lpx = (wn & 63) + nt * 8 + tg * 2;
                        int lm  = wm + mi * 16 + g;
                        sf[lpx * (MT + 1) + lm]           = acc[mi][nt][0];
                        sf[(lpx + 1) * (MT + 1) + lm]     = acc[mi][nt][1];
                        sf[lpx * (MT + 1) + lm + 8]       = acc[mi][nt][2];
                        sf[(lpx + 1) * (MT + 1) + lm + 8] = acc[mi][nt][3];
                    }
            }
        }
        __syncthreads();

        if (EPI == 0 || EPI == 1) {
            const int row = tid & 63;                 // px within half
            const int mc  = (tid >> 6) * (MT / 4);    // m slice
            const int px  = px0 + half * 64 + row;
            long ad = ((long)b * HWP + px) * Cs + m0 + mc;
            #pragma unroll
            for (int q = 0; q < MT / 32; q++) {
                union { uint4 u; __half h[8]; } pk;
                #pragma unroll
                for (int i = 0; i < 8; i++) {
                    int mm = mc + q * 8 + i;
                    float v = fmaf(sf[row * (MT + 1) + mm], scale[m0 + mm], shift[m0 + mm]);
                    v = (EPI == 0) ? tanha(v) : fmaxf(v, 0.f);
                    pk.h[i] = __float2half_rn(v);
                }
                *(uint4*)(O16 + ad + q * 8) = pk.u;
            }
        } else if (EPI == 2) {
            // wd fp16 channel-major [b][m][px]
            constexpr int TPR = 256 / MT;             // threads per m-row
            const int row = tid / TPR;                // 0..MT-1
            const int pc  = (tid % TPR) * (64 / TPR);
            const int gm  = m0 + row;
            if (gm < Mvalid) {
                const float sh = shift[gm];
                __half* wp = O16 + ((long)b * KKG + gm) * HWP + px0 + half * 64 + pc;
                #pragma unroll
                for (int q = 0; q < (64 / TPR) / 8; q++) {
                    union { uint4 u; __half h[8]; } pk;
                    #pragma unroll
                    for (int i = 0; i < 8; i++)
                        pk.h[i] = __float2half(sf[row * 65 + pc + q * 8 + i] + sh);
                    *(uint4*)(wp + q * 8) = pk.u;
                }
            }
        } else {
            const int row = tid >> 1;                 // m (MT=128 path)
            const int pc  = (tid & 1) << 5;
            const int gm  = m0 + row;
            const float sc = scale[gm], sh = shift[gm];
            const int pxb = px0 + half * 64 + pc;
            const long a = ((long)b * CC + gm) * HW + pxb;
            #pragma unroll
            for (int q = 0; q < 8; q++) {
                int px = pxb + q * 4;
                if (px < HW) {
                    float4 r4 = *(const float4*)(resid + a + q * 4);
                    float4 v;
                    v.x = fmaf(sf[row * 65 + pc + q * 4 + 0], sc, sh) + r4.x;
                    v.y = fmaf(sf[row * 65 + pc + q * 4 + 1], sc, sh) + r4.y;
                    v.z = fmaf(sf[row * 65 + pc + q * 4 + 2], sc, sh) + r4.z;
                    v.w = fmaf(sf[row * 65 + pc + q * 4 + 3], sc, sh) + r4.w;
                    *(float4*)(outF + a + q * 4) = v;
                }
            }
        }
        __syncthreads();
    }
}

// ---------------------------------------------------------------------------
// Involution + bn2 + tanh with packed f32x2 (channel pairs), 2 px per thread.
// ---------------------------------------------------------------------------
__global__ __launch_bounds__(224)
void involution_kernel()
{
    const int bg = blockIdx.y;
    const int b = bg >> 4, g = bg & 15;
    const int h0 = blockIdx.x * 8;
    const int tx = threadIdx.x;
    const int ty = threadIdx.y;
    const int tid = ty * 28 + tx;

    __shared__ float2 ys[8][14][64];

    const long ybase = (long)b * HWP * CC + g * GCC;
    for (int idx = tid; idx < 14 * 62; idx += 224) {
        int lh = idx / 62, lw = idx - lh * 62;
        int gh = h0 + lh - PADI, gw = lw - PADI;
        if (gh >= 0 && gh < HH && gw >= 0 && gw < WW) {
            long a = ybase + (long)(gh * WW + gw) * CC;
            union { uint4 u[2]; __half h[16]; } uy;
            uy.u[0] = *(const uint4*)(g_y16 + a);
            uy.u[1] = *(const uint4*)(g_y16 + a + 8);
            #pragma unroll
            for (int qp = 0; qp < 8; qp++)
                ys[qp][lh][lw] = make_float2(__half2float(uy.h[2*qp]),
                                             __half2float(uy.h[2*qp+1]));
        } else {
            #pragma unroll
            for (int qp = 0; qp < 8; qp++) ys[qp][lh][lw] = make_float2(0.f, 0.f);
        }
    }
    __syncthreads();

    const int h = h0 + ty;
    const int w0 = tx * 2;
    const int px = h * WW + w0;
    const __half* wdp = g_wd + ((long)b * KKG + g * (KK * KK)) * HWP + px;

    uint64_t acc[8][2];
    #pragma unroll
    for (int qp = 0; qp < 8; qp++) { acc[qp][0] = 0ull; acc[qp][1] = 0ull; }

    #pragma unroll
    for (int i = 0; i < KK; i++) {
        uint64_t wv2[KK][2];
        #pragma unroll
        for (int j = 0; j < KK; j++) {
            union { uint32_t u; __half h[2]; } t;
            t.u = *(const uint32_t*)(wdp + (long)(i * KK + j) * HWP);
            float f0 = __half2float(t.h[0]), f1 = __half2float(t.h[1]);
            wv2[j][0] = pack2(f0, f0);
            wv2[j][1] = pack2(f1, f1);
        }
        #pragma unroll
        for (int qp = 0; qp < 8; qp++) {
            float2 win2[8];
            *(float4*)(&win2[0]) = *(const float4*)(&ys[qp][ty + i][w0]);
            *(float4*)(&win2[2]) = *(const float4*)(&ys[qp][ty + i][w0 + 2]);
            *(float4*)(&win2[4]) = *(const float4*)(&ys[qp][ty + i][w0 + 4]);
            *(float4*)(&win2[6]) = *(const float4*)(&ys[qp][ty + i][w0 + 6]);
            #pragma unroll
            for (int j = 0; j < KK; j++) {
                fma2(acc[qp][0], wv2[j][0], *(const uint64_t*)(&win2[j]));
                fma2(acc[qp][1], wv2[j][1], *(const uint64_t*)(&win2[j + 1]));
            }
        }
    }

    #pragma unroll
    for (int p = 0; p < 2; p++) {
        long za = ((long)b * HWP + px + p) * CC + g * GCC;
        union { uint4 u[2]; __half hh[16]; } oz;
        #pragma unroll
        for (int qp = 0; qp < 8; qp++) {
            float lo, hi;
            unpack2(lo, hi, acc[qp][p]);
            int c0 = g * GCC + 2 * qp;
            oz.hh[2*qp]   = __float2half_rn(tanha(fmaf(lo, g_s2[c0],     g_h2[c0])));
            oz.hh[2*qp+1] = __float2half_rn(tanha(fmaf(hi, g_s2[c0 + 1], g_h2[c0 + 1])));
        }
        *(uint4*)(g_z16 + za)     = oz.u[0];
        *(uint4*)(g_z16 + za + 8) = oz.u[1];
    }
}

// ---------------------------------------------------------------------------
// Host
// ---------------------------------------------------------------------------
#define SMEM128 (3 * (128 + 128) * 64)   // 49152
#define SMEM64  (3 * (64 + 128) * 64)    // 36864

extern "C" void kernel_launch(void* const* d_in, const int* in_sizes, int n_in,
                              void* d_out, int out_size)
{
    const float* x     = (const float*)d_in[0];
    const float* w1    = (const float*)d_in[1];
    const float* b1    = (const float*)d_in[2];
    const float* bn1_g = (const float*)d_in[3];
    const float* bn1_b = (const float*)d_in[4];
    const float* bn1_m = (const float*)d_in[5];
    const float* bn1_v = (const float*)d_in[6];
    const float* red_w = (const float*)d_in[7];
    const float* red_b = (const float*)d_in[8];
    const float* rbn_g = (const float*)d_in[9];
    const float* rbn_b = (const float*)d_in[10];
    const float* rbn_m = (const float*)d_in[11];
    const float* rbn_v = (const float*)d_in[12];
    const float* span_w= (const float*)d_in[13];
    const float* span_b= (const float*)d_in[14];
    const float* bn2_g = (const float*)d_in[15];
    const float* bn2_b = (const float*)d_in[16];
    const float* bn2_m = (const float*)d_in[17];
    const float* bn2_v = (const float*)d_in[18];
    const float* w3    = (const float*)d_in[19];
    const float* b3    = (const float*)d_in[20];
    const float* bn3_g = (const float*)d_in[21];
    const float* bn3_b = (const float*)d_in[22];
    const float* bn3_m = (const float*)d_in[23];
    const float* bn3_v = (const float*)d_in[24];
    float* out = (float*)d_out;

    __half *x16,*y16,*r16,*z16,*wd;
    __half *w1h,*w3h,*rwh,*swh;
    float *s1,*h1,*sr,*hr,*s3,*h3;
    cudaGetSymbolAddress((void**)&x16, g_x16);
    cudaGetSymbolAddress((void**)&y16, g_y16);
    cudaGetSymbolAddress((void**)&r16, g_r16);
    cudaGetSymbolAddress((void**)&z16, g_z16);
    cudaGetSymbolAddress((void**)&wd,  g_wd);
    cudaGetSymbolAddress((void**)&w1h, g_w1h);
    cudaGetSymbolAddress((void**)&w3h, g_w3h);
    cudaGetSymbolAddress((void**)&rwh, g_rwh);
    cudaGetSymbolAddress((void**)&swh, g_swh);
    cudaGetSymbolAddress((void**)&s1, g_s1);  cudaGetSymbolAddress((void**)&h1, g_h1);
    cudaGetSymbolAddress((void**)&sr, g_sr);  cudaGetSymbolAddress((void**)&hr, g_hr);
    cudaGetSymbolAddress((void**)&s3, g_s3);  cudaGetSymbolAddress((void**)&h3, g_h3);

    cudaFuncSetAttribute((const void*)gemm_tc<0,128>, cudaFuncAttributeMaxDynamicSharedMemorySize, SMEM128);
    cudaFuncSetAttribute((const void*)gemm_tc<1,64>,  cudaFuncAttributeMaxDynamicSharedMemorySize, SMEM64);
    cudaFuncSetAttribute((const void*)gemm_tc<2,128>, cudaFuncAttributeMaxDynamicSharedMemorySize, SMEM128);
    cudaFuncSetAttribute((const void*)gemm_tc<2,64>,  cudaFuncAttributeMaxDynamicSharedMemorySize, SMEM64);
    cudaFuncSetAttribute((const void*)gemm_tc<3,128>, cudaFuncAttributeMaxDynamicSharedMemorySize, SMEM128);

    precompute_kernel<<<1, 256>>>(b1, bn1_g, bn1_b, bn1_m, bn1_v,
                                  red_b, rbn_g, rbn_b, rbn_m, rbn_v,
                                  bn2_g, bn2_b, bn2_m, bn2_v,
                                  b3, bn3_g, bn3_b, bn3_m, bn3_v);
    prep_weights<<<256, 256>>>(w1, w3, red_w, span_w);
    convert_x_kernel<<<dim3(HW/32, CC/32, BB), dim3(32, 8)>>>(x);

    const int NPX = HWP / 128;   // 25 px tiles

    // y = tanh(bn1(W1 @ x))
    gemm_tc<0,128><<<dim3(NPX, 2, BB), 256, SMEM128>>>(
        w1h, x16, CC, CC, CC, 0, nullptr, y16, s1, h1, nullptr);

    // r = relu(bn_red(RedW @ y))  -- exact M=64 tile, no waste
    gemm_tc<1,64><<<dim3(NPX, 1, BB), 256, SMEM64>>>(
        rwh, y16, CC, RED, RED, 0, nullptr, r16, sr, hr, nullptr);

    // wd = SpanW @ r + span_b : rows 0..767 with 128-tiles, 768..831 with a 64-tile
    gemm_tc<2,128><<<dim3(NPX, 6, BB), 256, SMEM128>>>(
        swh, r16, RED, KKG, KKG, 0, nullptr, wd, span_b, span_b, nullptr);
    gemm_tc<2,64><<<dim3(NPX, 1, BB), 256, SMEM64>>>(
        swh, r16, RED, KKG, KKG, 768, nullptr, wd, span_b, span_b, nullptr);

    // z = tanh(bn2(involution(y, wd)))
    involution_kernel<<<dim3(HH/8, BB*GG), dim3(28, 8)>>>();

    // out = bn3(W3 @ z) + x
    gemm_tc<3,128><<<dim3(NPX, 2, BB), 256, SMEM128>>>(
        w3h, z16, CC, CC, CC, 0, out, nullptr, s3, h3, x);
}

// round 15
// speedup vs baseline: 1.0159x; 1.0159x over previous
#include <cuda_runtime.h>
#include <cuda_bf16.h>
#include <cuda_fp16.h>
#include <math.h>
#include <stdint.h>

// ---------------------------------------------------------------------------
// Problem constants
// ---------------------------------------------------------------------------
#define BB   16
#define CC   256
#define HH   56
#define WW   56
#define HW   3136
#define HWP  3200            // pixel dim padded
#define KK   7
#define GCC  16
#define GG   16
#define RED  64
#define KKG  784
#define PADI 3

// ---------------------------------------------------------------------------
// Scratch. Activations pixel-major [b][px][ch] fp16.
// wd channel-major [b][784][px] fp16. Weights fp16.
// ---------------------------------------------------------------------------
__device__ __align__(16) __half g_x16[BB*HWP*CC];
__device__ __align__(16) __half g_y16[BB*HWP*CC];
__device__ __align__(16) __half g_r16[BB*HWP*RED];
__device__ __align__(16) __half g_z16[BB*HWP*CC];
__device__ __align__(16) __half g_wd[(size_t)BB*KKG*HWP];

__device__ __align__(16) __half g_w1h[CC*CC];
__device__ __align__(16) __half g_w3h[CC*CC];
__device__ __align__(16) __half g_rwh[128*CC];
__device__ __align__(16) __half g_swh[896*RED];

__device__ float g_s1[CC], g_h1[CC];
__device__ float g_sr[RED], g_hr[RED];
__device__ float g_s2[CC], g_h2[CC];
__device__ float g_s3[CC], g_h3[CC];

// ---------------------------------------------------------------------------
// PTX helpers
// ---------------------------------------------------------------------------
__device__ __forceinline__ uint32_t s2u(const void* p) {
    uint32_t a;
    asm("{ .reg .u64 t; cvta.to.shared.u64 t, %1; cvt.u32.u64 %0, t; }" : "=r"(a) : "l"(p));
    return a;
}

__device__ __forceinline__ void cpasync16(uint32_t saddr, const void* g) {
    asm volatile("cp.async.cg.shared.global [%0], [%1], 16;" :: "r"(saddr), "l"(g));
}

__device__ __forceinline__ void ldsm4(uint32_t* r, uint32_t a) {
    asm volatile("ldmatrix.sync.aligned.m8n8.x4.shared.b16 {%0,%1,%2,%3}, [%4];"
                 : "=r"(r[0]), "=r"(r[1]), "=r"(r[2]), "=r"(r[3]) : "r"(a));
}

__device__ __forceinline__ void mma_f16(float* c, const uint32_t* a, const uint32_t* b) {
    asm volatile("mma.sync.aligned.m16n8k16.row.col.f32.f16.f16.f32 "
        "{%0,%1,%2,%3}, {%4,%5,%6,%7}, {%8,%9}, {%0,%1,%2,%3};"
        : "+f"(c[0]), "+f"(c[1]), "+f"(c[2]), "+f"(c[3])
        : "r"(a[0]), "r"(a[1]), "r"(a[2]), "r"(a[3]), "r"(b[0]), "r"(b[1]));
}

__device__ __forceinline__ float tanha(float x) {
    float r; asm("tanh.approx.f32 %0, %1;" : "=f"(r) : "f"(x)); return r;
}

// Packed f32x2 (Blackwell family)
__device__ __forceinline__ void fma2(uint64_t& d, uint64_t a, uint64_t b) {
    asm("fma.rn.f32x2 %0, %1, %2, %0;" : "+l"(d) : "l"(a), "l"(b));
}
__device__ __forceinline__ uint64_t pack2(float x, float y) {
    uint64_t r; asm("mov.b64 %0, {%1, %2};" : "=l"(r) : "f"(x), "f"(y)); return r;
}
__device__ __forceinline__ void unpack2(float& x, float& y, uint64_t v) {
    asm("mov.b64 {%0, %1}, %2;" : "=f"(x), "=f"(y) : "l"(v));
}

// SW128-style swizzle for 128-byte rows: c16 (0..7) ^= (r & 7)
__device__ __forceinline__ uint32_t soff128(int r, int c16) {
    return (uint32_t)(r * 128) + (uint32_t)(((c16 ^ (r & 7)) & 7) << 4);
}

// ---------------------------------------------------------------------------
// Fold BN (+conv bias) into per-channel scale/shift
// ---------------------------------------------------------------------------
__global__ void precompute_kernel(
    const float* __restrict__ b1,
    const float* __restrict__ g1, const float* __restrict__ be1,
    const float* __restrict__ m1, const float* __restrict__ v1,
    const float* __restrict__ redb,
    const float* __restrict__ rg, const float* __restrict__ rb,
    const float* __restrict__ rm, const float* __restrict__ rv,
    const float* __restrict__ g2, const float* __restrict__ be2,
    const float* __restrict__ m2, const float* __restrict__ v2,
    const float* __restrict__ b3,
    const float* __restrict__ g3, const float* __restrict__ be3,
    const float* __restrict__ m3, const float* __restrict__ v3)
{
    int c = threadIdx.x;
    if (c < CC) {
        float s = g1[c] * rsqrtf(v1[c] + 1e-5f);
        g_s1[c] = s; g_h1[c] = b1[c]*s + be1[c] - m1[c]*s;
        s = g2[c] * rsqrtf(v2[c] + 1e-5f);
        g_s2[c] = s; g_h2[c] = be2[c] - m2[c]*s;
        s = g3[c] * rsqrtf(v3[c] + 1e-5f);
        g_s3[c] = s; g_h3[c] = b3[c]*s + be3[c] - m3[c]*s;
    }
    if (c < RED) {
        float s = rg[c] * rsqrtf(rv[c] + 1e-5f);
        g_sr[c] = s; g_hr[c] = redb[c]*s + rb[c] - rm[c]*s;
    }
}

// ---------------------------------------------------------------------------
// Convert weights to fp16 (zero padding of M)
// ---------------------------------------------------------------------------
__global__ void prep_weights(const float* __restrict__ w1, const float* __restrict__ w3,
                             const float* __restrict__ redw, const float* __restrict__ spanw)
{
    int i = blockIdx.x * 256 + threadIdx.x;
    if (i < CC * CC) {
        g_w1h[i] = __float2half_rn(w1[i]);
        g_w3h[i] = __float2half_rn(w3[i]);
    }
    if (i < 128 * CC) {
        int r = i >> 8;
        g_rwh[i] = __float2half_rn((r < RED) ? redw[i] : 0.f);
    }
    if (i < 896 * RED) {
        int r = i / RED;
        g_swh[i] = __float2half_rn((r < KKG) ? spanw[i] : 0.f);
    }
}

// ---------------------------------------------------------------------------
// Transpose input x: [b][c][px] fp32 -> [b][px][c] fp16
// ---------------------------------------------------------------------------
__global__ void convert_x_kernel(const float* __restrict__ x)
{
    __shared__ float t[32][33];
    const int b = blockIdx.z, px0 = blockIdx.x * 32, c0 = blockIdx.y * 32;
    #pragma unroll
    for (int i = 0; i < 4; i++) {
        int cy = threadIdx.y + i * 8;
        t[cy][threadIdx.x] = x[((long)(b * CC + c0 + cy)) * HW + px0 + threadIdx.x];
    }
    __syncthreads();
    #pragma unroll
    for (int i = 0; i < 4; i++) {
        int py = threadIdx.y + i * 8;
        long a = ((long)b * HWP + px0 + py) * CC + c0 + threadIdx.x;
        g_x16[a] = __float2half_rn(t[threadIdx.x][py]);
    }
}

// ---------------------------------------------------------------------------
// fp16 GEMM on mma.sync: D[m, px] = W[m,:] . B[px,:]
// Block MT x 128 (m x px), 8 warps ((MT/2) x 32 warp tiles), K-chunk 64
// (4 k16 steps), 3-stage cp.async, SW128 swizzle on 128B rows.
// ---------------------------------------------------------------------------
#define KC 64

template<int EPI, int MT>
__global__ __launch_bounds__(256, 2)
void gemm_tc(const __half* __restrict__ Ah, const __half* __restrict__ Bm,
             int Ka, int Mvalid, int Cs, int moff,
             float* __restrict__ outF, __half* __restrict__ O16,
             const float* __restrict__ scale, const float* __restrict__ shift,
             const float* __restrict__ resid)
{
    constexpr int MI   = MT / 32;             // 16-row m-subtiles per warp
    constexpr int OFFB = MT * 128;            // A bytes per stage
    constexpr int STB  = (MT + 128) * 128;    // stage bytes

    extern __shared__ char smem[];
    const int tid = threadIdx.x, wid = tid >> 5, lane = tid & 31;
    const int b = blockIdx.z;
    const int m0 = blockIdx.y * MT + moff;
    const int px0 = blockIdx.x << 7;
    const uint32_t sb = s2u(smem);

    const int wm = (wid & 1) * (MT / 2);
    const int wn = (wid >> 1) * 32;

    const int lrow = tid >> 3;                // 0..31
    const int lc16 = tid & 7;                 // 0..7
    const long bbase = (long)b * HWP + px0;

    float acc[MI][4][4];
    #pragma unroll
    for (int i = 0; i < MI; i++)
        #pragma unroll
        for (int j = 0; j < 4; j++)
            #pragma unroll
            for (int q = 0; q < 4; q++) acc[i][j][q] = 0.f;

    auto issue = [&](int kt, int s) {
        const int k0 = kt * KC;
        const uint32_t sbase = sb + s * STB;
        #pragma unroll
        for (int p = 0; p < MT / 32; p++) {
            int r = lrow + p * 32;
            cpasync16(sbase + soff128(r, lc16),
                      Ah + (long)(m0 + r) * Ka + k0 + lc16 * 8);
        }
        #pragma unroll
        for (int p = 0; p < 4; p++) {
            int r = lrow + p * 32;
            cpasync16(sbase + OFFB + soff128(r, lc16),
                      Bm + (bbase + r) * Ka + k0 + lc16 * 8);
        }
        asm volatile("cp.async.commit_group;" ::: "memory");
    };

    const int nk = Ka / KC;
    issue(0, 0);
    if (nk > 1) issue(1, 1);

    for (int t = 0; t < nk; t++) {
        if (t + 1 < nk) asm volatile("cp.async.wait_group 1;" ::: "memory");
        else            asm volatile("cp.async.wait_group 0;" ::: "memory");
        __syncthreads();
        if (t + 2 < nk) issue(t + 2, (t + 2) % 3);

        const uint32_t sbase = sb + (t % 3) * STB;

        // preload all B fragments for the chunk (warp's 32 px, 4 k16 steps)
        uint32_t bf[4][2][4];
        #pragma unroll
        for (int kb = 0; kb < 4; kb++)
            #pragma unroll
            for (int pr = 0; pr < 2; pr++) {
                int n = wn + pr * 16 + (lane & 7) + ((lane >> 4) << 3);
                int c = kb * 2 + ((lane >> 3) & 1);
                ldsm4(bf[kb][pr], sbase + OFFB + soff128(n, c));
            }

        #pragma unroll
        for (int kb = 0; kb < 4; kb++) {
            #pragma unroll
            for (int mi = 0; mi < MI; mi++) {
                int r = wm + mi * 16 + (lane & 15);
                int c = kb * 2 + (lane >> 4);
                uint32_t ah[4];
                ldsm4(ah, sbase + soff128(r, c));
                #pragma unroll
                for (int nt = 0; nt < 4; nt++)
                    mma_f16(acc[mi][nt], ah, &bf[kb][nt >> 1][(nt & 1) * 2]);
            }
        }
    }

    // ======================= smem-staged epilogue (two px halves) ========
    __syncthreads();
    float* sf = (float*)smem;
    const int g = lane >> 2, tg = lane & 3;

    #pragma unroll 1
    for (int half = 0; half < 2; half++) {
        if ((wn >> 6) == half) {
            if (EPI >= 2) {
                // [m][px] pitch 65
                #pragma unroll
                for (int mi = 0; mi < MI; mi++)
                    #pragma unroll
                    for (int nt = 0; nt < 4; nt++) {
                        int lpx = (wn & 63) + nt * 8 + tg * 2;
                        int lm  = wm + mi * 16 + g;
                        sf[lm * 65 + lpx]           = acc[mi][nt][0];
                        sf[lm * 65 + lpx + 1]       = acc[mi][nt][1];
                        sf[(lm + 8) * 65 + lpx]     = acc[mi][nt][2];
                        sf[(lm + 8) * 65 + lpx + 1] = acc[mi][nt][3];
                    }
            } else {
                // [px][m] pitch MT+1
                #pragma unroll
                for (int mi = 0; mi < MI; mi++)
                    #pragma unroll
                    for (int nt = 0; nt < 4; nt++) {
                        int lpx = (wn & 63) + nt * 8 + tg * 2;
                        int lm  = wm + mi * 16 + g;
                        sf[lpx * (MT + 1) + lm]           = acc[mi][nt][0];
                        sf[(lpx + 1) * (MT + 1) + lm]     = acc[mi][nt][1];
                        sf[lpx * (MT + 1) + lm + 8]       = acc[mi][nt][2];
                        sf[(lpx + 1) * (MT + 1) + lm + 8] = acc[mi][nt][3];
                    }
            }
        }
        __syncthreads();

        if (EPI == 0 || EPI == 1) {
            const int row = tid & 63;
            const int mc  = (tid >> 6) * (MT / 4);
            const int px  = px0 + half * 64 + row;
            long ad = ((long)b * HWP + px) * Cs + m0 + mc;
            #pragma unroll
            for (int q = 0; q < MT / 32; q++) {
                union { uint4 u; __half h[8]; } pk;
                #pragma unroll
                for (int i = 0; i < 8; i++) {
                    int mm = mc + q * 8 + i;
                    float v = fmaf(sf[row * (MT + 1) + mm], scale[m0 + mm], shift[m0 + mm]);
                    v = (EPI == 0) ? tanha(v) : fmaxf(v, 0.f);
                    pk.h[i] = __float2half_rn(v);
                }
                *(uint4*)(O16 + ad + q * 8) = pk.u;
            }
        } else if (EPI == 2) {
            constexpr int TPR = 256 / MT;
            const int row = tid / TPR;
            const int pc  = (tid % TPR) * (64 / TPR);
            const int gm  = m0 + row;
            if (gm < Mvalid) {
                const float sh = shift[gm];
                __half* wp = O16 + ((long)b * KKG + gm) * HWP + px0 + half * 64 + pc;
                #pragma unroll
                for (int q = 0; q < (64 / TPR) / 8; q++) {
                    union { uint4 u; __half h[8]; } pk;
                    #pragma unroll
                    for (int i = 0; i < 8; i++)
                        pk.h[i] = __float2half(sf[row * 65 + pc + q * 8 + i] + sh);
                    *(uint4*)(wp + q * 8) = pk.u;
                }
            }
        } else {
            const int row = tid >> 1;
            const int pc  = (tid & 1) << 5;
            const int gm  = m0 + row;
            const float sc = scale[gm], sh = shift[gm];
            const int pxb = px0 + half * 64 + pc;
            const long a = ((long)b * CC + gm) * HW + pxb;
            #pragma unroll
            for (int q = 0; q < 8; q++) {
                int px = pxb + q * 4;
                if (px < HW) {
                    float4 r4 = *(const float4*)(resid + a + q * 4);
                    float4 v;
                    v.x = fmaf(sf[row * 65 + pc + q * 4 + 0], sc, sh) + r4.x;
                    v.y = fmaf(sf[row * 65 + pc + q * 4 + 1], sc, sh) + r4.y;
                    v.z = fmaf(sf[row * 65 + pc + q * 4 + 2], sc, sh) + r4.z;
                    v.w = fmaf(sf[row * 65 + pc + q * 4 + 3], sc, sh) + r4.w;
                    *(float4*)(outF + a + q * 4) = v;
                }
            }
        }
        __syncthreads();
    }
}

// ---------------------------------------------------------------------------
// Involution + bn2 + tanh with packed f32x2 (channel pairs), 2 px per thread.
// ---------------------------------------------------------------------------
__global__ __launch_bounds__(224)
void involution_kernel()
{
    const int bg = blockIdx.y;
    const int b = bg >> 4, g = bg & 15;
    const int h0 = blockIdx.x * 8;
    const int tx = threadIdx.x;
    const int ty = threadIdx.y;
    const int tid = ty * 28 + tx;

    __shared__ float2 ys[8][14][64];

    const long ybase = (long)b * HWP * CC + g * GCC;
    for (int idx = tid; idx < 14 * 62; idx += 224) {
        int lh = idx / 62, lw = idx - lh * 62;
        int gh = h0 + lh - PADI, gw = lw - PADI;
        if (gh >= 0 && gh < HH && gw >= 0 && gw < WW) {
            long a = ybase + (long)(gh * WW + gw) * CC;
            union { uint4 u[2]; __half h[16]; } uy;
            uy.u[0] = *(const uint4*)(g_y16 + a);
            uy.u[1] = *(const uint4*)(g_y16 + a + 8);
            #pragma unroll
            for (int qp = 0; qp < 8; qp++)
                ys[qp][lh][lw] = make_float2(__half2float(uy.h[2*qp]),
                                             __half2float(uy.h[2*qp+1]));
        } else {
            #pragma unroll
            for (int qp = 0; qp < 8; qp++) ys[qp][lh][lw] = make_float2(0.f, 0.f);
        }
    }
    __syncthreads();

    const int h = h0 + ty;
    const int w0 = tx * 2;
    const int px = h * WW + w0;
    const __half* wdp = g_wd + ((long)b * KKG + g * (KK * KK)) * HWP + px;

    uint64_t acc[8][2];
    #pragma unroll
    for (int qp = 0; qp < 8; qp++) { acc[qp][0] = 0ull; acc[qp][1] = 0ull; }

    #pragma unroll
    for (int i = 0; i < KK; i++) {
        uint64_t wv2[KK][2];
        #pragma unroll
        for (int j = 0; j < KK; j++) {
            union { uint32_t u; __half h[2]; } t;
            t.u = *(const uint32_t*)(wdp + (long)(i * KK + j) * HWP);
            float f0 = __half2float(t.h[0]), f1 = __half2float(t.h[1]);
            wv2[j][0] = pack2(f0, f0);
            wv2[j][1] = pack2(f1, f1);
        }
        #pragma unroll
        for (int qp = 0; qp < 8; qp++) {
            float2 win2[8];
            *(float4*)(&win2[0]) = *(const float4*)(&ys[qp][ty + i][w0]);
            *(float4*)(&win2[2]) = *(const float4*)(&ys[qp][ty + i][w0 + 2]);
            *(float4*)(&win2[4]) = *(const float4*)(&ys[qp][ty + i][w0 + 4]);
            *(float4*)(&win2[6]) = *(const float4*)(&ys[qp][ty + i][w0 + 6]);
            #pragma unroll
            for (int j = 0; j < KK; j++) {
                fma2(acc[qp][0], wv2[j][0], *(const uint64_t*)(&win2[j]));
                fma2(acc[qp][1], wv2[j][1], *(const uint64_t*)(&win2[j + 1]));
            }
        }
    }

    #pragma unroll
    for (int p = 0; p < 2; p++) {
        long za = ((long)b * HWP + px + p) * CC + g * GCC;
        union { uint4 u[2]; __half hh[16]; } oz;
        #pragma unroll
        for (int qp = 0; qp < 8; qp++) {
            float lo, hi;
            unpack2(lo, hi, acc[qp][p]);
            int c0 = g * GCC + 2 * qp;
            oz.hh[2*qp]   = __float2half_rn(tanha(fmaf(lo, g_s2[c0],     g_h2[c0])));
            oz.hh[2*qp+1] = __float2half_rn(tanha(fmaf(hi, g_s2[c0 + 1], g_h2[c0 + 1])));
        }
        *(uint4*)(g_z16 + za)     = oz.u[0];
        *(uint4*)(g_z16 + za + 8) = oz.u[1];
    }
}

// ---------------------------------------------------------------------------
// Host
// ---------------------------------------------------------------------------
#define SMEM128 (3 * (128 + 128) * 128)   // 98304
#define SMEM64  (3 * (64 + 128) * 128)    // 73728

extern "C" void kernel_launch(void* const* d_in, const int* in_sizes, int n_in,
                              void* d_out, int out_size)
{
    const float* x     = (const float*)d_in[0];
    const float* w1    = (const float*)d_in[1];
    const float* b1    = (const float*)d_in[2];
    const float* bn1_g = (const float*)d_in[3];
    const float* bn1_b = (const float*)d_in[4];
    const float* bn1_m = (const float*)d_in[5];
    const float* bn1_v = (const float*)d_in[6];
    const float* red_w = (const float*)d_in[7];
    const float* red_b = (const float*)d_in[8];
    const float* rbn_g = (const float*)d_in[9];
    const float* rbn_b = (const float*)d_in[10];
    const float* rbn_m = (const float*)d_in[11];
    const float* rbn_v = (const float*)d_in[12];
    const float* span_w= (const float*)d_in[13];
    const float* span_b= (const float*)d_in[14];
    const float* bn2_g = (const float*)d_in[15];
    const float* bn2_b = (const float*)d_in[16];
    const float* bn2_m = (const float*)d_in[17];
    const float* bn2_v = (const float*)d_in[18];
    const float* w3    = (const float*)d_in[19];
    const float* b3    = (const float*)d_in[20];
    const float* bn3_g = (const float*)d_in[21];
    const float* bn3_b = (const float*)d_in[22];
    const float* bn3_m = (const float*)d_in[23];
    const float* bn3_v = (const float*)d_in[24];
    float* out = (float*)d_out;

    __half *x16,*y16,*r16,*z16,*wd;
    __half *w1h,*w3h,*rwh,*swh;
    float *s1,*h1,*sr,*hr,*s3,*h3;
    cudaGetSymbolAddress((void**)&x16, g_x16);
    cudaGetSymbolAddress((void**)&y16, g_y16);
    cudaGetSymbolAddress((void**)&r16, g_r16);
    cudaGetSymbolAddress((void**)&z16, g_z16);
    cudaGetSymbolAddress((void**)&wd,  g_wd);
    cudaGetSymbolAddress((void**)&w1h, g_w1h);
    cudaGetSymbolAddress((void**)&w3h, g_w3h);
    cudaGetSymbolAddress((void**)&rwh, g_rwh);
    cudaGetSymbolAddress((void**)&swh, g_swh);
    cudaGetSymbolAddress((void**)&s1, g_s1);  cudaGetSymbolAddress((void**)&h1, g_h1);
    cudaGetSymbolAddress((void**)&sr, g_sr);  cudaGetSymbolAddress((void**)&hr, g_hr);
    cudaGetSymbolAddress((void**)&s3, g_s3);  cudaGetSymbolAddress((void**)&h3, g_h3);

    cudaFuncSetAttribute((const void*)gemm_tc<0,128>, cudaFuncAttributeMaxDynamicSharedMemorySize, SMEM128);
    cudaFuncSetAttribute((const void*)gemm_tc<1,64>,  cudaFuncAttributeMaxDynamicSharedMemorySize, SMEM64);
    cudaFuncSetAttribute((const void*)gemm_tc<2,128>, cudaFuncAttributeMaxDynamicSharedMemorySize, SMEM128);
    cudaFuncSetAttribute((const void*)gemm_tc<2,64>,  cudaFuncAttributeMaxDynamicSharedMemorySize, SMEM64);
    cudaFuncSetAttribute((const void*)gemm_tc<3,128>, cudaFuncAttributeMaxDynamicSharedMemorySize, SMEM128);

    precompute_kernel<<<1, 256>>>(b1, bn1_g, bn1_b, bn1_m, bn1_v,
                                  red_b, rbn_g, rbn_b, rbn_m, rbn_v,
                                  bn2_g, bn2_b, bn2_m, bn2_v,
                                  b3, bn3_g, bn3_b, bn3_m, bn3_v);
    prep_weights<<<256, 256>>>(w1, w3, red_w, span_w);
    convert_x_kernel<<<dim3(HW/32, CC/32, BB), dim3(32, 8)>>>(x);

    const int NPX = HWP / 128;   // 25 px tiles

    // y = tanh(bn1(W1 @ x))
    gemm_tc<0,128><<<dim3(NPX, 2, BB), 256, SMEM128>>>(
        w1h, x16, CC, CC, CC, 0, nullptr, y16, s1, h1, nullptr);

    // r = relu(bn_red(RedW @ y))  -- exact M=64 tile
    gemm_tc<1,64><<<dim3(NPX, 1, BB), 256, SMEM64>>>(
        rwh, y16, CC, RED, RED, 0, nullptr, r16, sr, hr, nullptr);

    // wd = SpanW @ r + span_b : rows 0..767 with 128-tiles, 768..831 with a 64-tile
    gemm_tc<2,128><<<dim3(NPX, 6, BB), 256, SMEM128>>>(
        swh, r16, RED, KKG, KKG, 0, nullptr, wd, span_b, span_b, nullptr);
    gemm_tc<2,64><<<dim3(NPX, 1, BB), 256, SMEM64>>>(
        swh, r16, RED, KKG, KKG, 768, nullptr, wd, span_b, span_b, nullptr);

    // z = tanh(bn2(involution(y, wd)))
    involution_kernel<<<dim3(HH/8, BB*GG), dim3(28, 8)>>>();

    // out = bn3(W3 @ z) + x
    gemm_tc<3,128><<<dim3(NPX, 2, BB), 256, SMEM128>>>(
        w3h, z16, CC, CC, CC, 0, out, nullptr, s3, h3, x);
}